// round 3
// baseline (speedup 1.0000x reference)
#include <cuda_runtime.h>
#include <cuda_bf16.h>
#include <cstdint>

// Problem constants
#define BB 4
#define TT 2048
#define DD 1024
#define HH 16
#define DKK 64
#define DVV 128
#define KK (HH*DKK)   // 1024
#define VV (HH*DVV)   // 2048
#define MM (BB*TT)    // 8192

// ---------------- scratch (device globals; no allocation) ----------------
__device__ float g_r [MM*KK];
__device__ float g_k [MM*KK];
__device__ float g_w [MM*KK];
__device__ float g_xw[MM*DD];
__device__ float g_v [MM*VV];
__device__ float g_g [MM*VV];
__device__ float g_o [MM*VV];
__device__ float g_h1[MM*32];
__device__ float g_h2[MM*32];

// ---------------- GEMM: C[M,N] = f( Aload(A)[M,Kd] @ B[Kd,N] ) ----------------
// AMODE: 0 = plain A; 1 = token-shift modulated: a = x + (x_prev - x)*mu[k]
// EPI:   0 = store acc
//        1 = tanh(acc)
//        2 = xw-combine: C = X + (X_prev - X) * (acc + bias[n])
//        3 = -exp(acc + bias[n])
#define GBM 128
#define GBN 128
#define GBK 8

template<int AMODE, int EPI>
__global__ __launch_bounds__(256)
void gemm_kernel(const float* __restrict__ A, const float* __restrict__ B,
                 float* __restrict__ C, int M, int N, int Kd,
                 const float* __restrict__ mu, const float* __restrict__ bias,
                 const float* __restrict__ X)
{
    __shared__ float As[GBK][GBM];
    __shared__ float Bs[GBK][GBN + 4];

    const int tid = threadIdx.x;           // 256 threads
    const int tx = tid & 15;               // 0..15
    const int ty = tid >> 4;               // 0..15

    const int rowA = tid >> 1;             // 0..127
    const int colA = (tid & 1) * 4;        // 0 or 4
    const int rowB = tid >> 5;             // 0..7
    const int colB = (tid & 31) * 4;       // 0..124

    const int gRowA = blockIdx.y * GBM + rowA;   // M is multiple of 128
    const bool isT0 = ((gRowA & (TT - 1)) == 0); // first token of a batch row

    float acc[8][8];
#pragma unroll
    for (int i = 0; i < 8; i++)
#pragma unroll
        for (int j = 0; j < 8; j++) acc[i][j] = 0.f;

    const int gnB = blockIdx.x * GBN + colB;

    for (int k0 = 0; k0 < Kd; k0 += GBK) {
        // ---- load A tile (optionally token-shift modulated) ----
        const float* aptr = A + (size_t)gRowA * Kd + (k0 + colA);
        float4 a = *(const float4*)aptr;
        if (AMODE == 1) {
            float4 p;
            if (isT0) { p.x = p.y = p.z = p.w = 0.f; }
            else      { p = *(const float4*)(aptr - Kd); }
            float4 m4 = *(const float4*)(mu + k0 + colA);
            a.x = a.x + (p.x - a.x) * m4.x;
            a.y = a.y + (p.y - a.y) * m4.y;
            a.z = a.z + (p.z - a.z) * m4.z;
            a.w = a.w + (p.w - a.w) * m4.w;
        }
        As[colA + 0][rowA] = a.x;
        As[colA + 1][rowA] = a.y;
        As[colA + 2][rowA] = a.z;
        As[colA + 3][rowA] = a.w;

        // ---- load B tile (guard N for N=32 cases) ----
        float4 b;
        if (gnB < N) b = *(const float4*)(B + (size_t)(k0 + rowB) * N + gnB);
        else { b.x = b.y = b.z = b.w = 0.f; }
        *(float4*)&Bs[rowB][colB] = b;

        __syncthreads();

#pragma unroll
        for (int kk = 0; kk < GBK; ++kk) {
            float ra[8], rb[8];
            *(float4*)&ra[0] = *(const float4*)&As[kk][ty * 8];
            *(float4*)&ra[4] = *(const float4*)&As[kk][ty * 8 + 4];
            *(float4*)&rb[0] = *(const float4*)&Bs[kk][tx * 8];
            *(float4*)&rb[4] = *(const float4*)&Bs[kk][tx * 8 + 4];
#pragma unroll
            for (int i = 0; i < 8; i++)
#pragma unroll
                for (int j = 0; j < 8; j++)
                    acc[i][j] += ra[i] * rb[j];
        }
        __syncthreads();
    }

    // ---- epilogue ----
#pragma unroll
    for (int i = 0; i < 8; i++) {
        const int row = blockIdx.y * GBM + ty * 8 + i;
        const bool rT0 = ((row & (TT - 1)) == 0);
#pragma unroll
        for (int j = 0; j < 8; j++) {
            const int col = blockIdx.x * GBN + tx * 8 + j;
            if (col >= N) continue;
            const size_t cidx = (size_t)row * N + col;
            float vacc = acc[i][j];
            if (EPI == 0) {
                C[cidx] = vacc;
            } else if (EPI == 1) {
                C[cidx] = tanhf(vacc);
            } else if (EPI == 2) {
                float lam = vacc + bias[col];
                float xv = X[cidx];
                float xp = rT0 ? 0.f : X[cidx - N];
                C[cidx] = xv + (xp - xv) * lam;
            } else if (EPI == 3) {
                C[cidx] = -expf(vacc + bias[col]);
            }
        }
    }
}

// ---------------- recurrent scan ----------------
// grid = B*H CTAs; 256 threads: (half = tid/128) in {0,1} covers k in [half*32, half*32+32),
// vv = tid%128 covers DV. State h[32] per thread in registers.
__global__ __launch_bounds__(256)
void scan_kernel(const float* __restrict__ r, const float* __restrict__ k,
                 const float* __restrict__ v, const float* __restrict__ w,
                 const float* __restrict__ bonus, float* __restrict__ o)
{
    const int bh = blockIdx.x;
    const int b = bh / HH;
    const int hh = bh % HH;
    const int tid = threadIdx.x;
    const int vv = tid & 127;
    const int half = tid >> 7;
    const int kbase = half * 32;

    __shared__ float s_r[DKK], s_k[DKK], s_uk[DKK], s_ew[DKK];
    __shared__ float s_v[DVV], s_part[DVV];
    __shared__ float s_u[DKK];
    __shared__ float s_dp[2];

    if (tid < DKK) s_u[tid] = bonus[hh * DKK + tid];
    __syncthreads();

    float h[32];
#pragma unroll
    for (int i = 0; i < 32; i++) h[i] = 0.f;

    const size_t rb = (size_t)(b * TT) * KK + hh * DKK;
    const size_t vb = (size_t)(b * TT) * VV + hh * DVV;

    for (int t = 0; t < TT; ++t) {
        const size_t ro = rb + (size_t)t * KK;
        const size_t vo = vb + (size_t)t * VV;

        if (tid < DKK) {
            float kv_ = k[ro + tid];
            float rv_ = r[ro + tid];
            float uk_ = s_u[tid] * kv_;
            s_r[tid] = rv_;
            s_k[tid] = kv_;
            s_uk[tid] = uk_;
            s_ew[tid] = expf(w[ro + tid]);
            float dp = rv_ * uk_;
#pragma unroll
            for (int off = 16; off > 0; off >>= 1)
                dp += __shfl_xor_sync(0xffffffff, dp, off);
            if ((tid & 31) == 0) s_dp[tid >> 5] = dp;
        }
        if (tid >= 128) s_v[tid - 128] = v[vo + (tid - 128)];
        __syncthreads();

        const float vvv = s_v[vv];
        float accp = 0.f;
#pragma unroll
        for (int i = 0; i < 32; i++) {
            const int kkk = kbase + i;
            const float hv = h[i];
            accp += s_r[kkk] * hv;
            h[i] = hv * s_ew[kkk] + s_k[kkk] * vvv;
        }
        if (half == 1) s_part[vv] = accp;
        __syncthreads();
        if (half == 0) {
            const float d = s_dp[0] + s_dp[1];
            o[vo + vv] = accp + s_part[vv] + d * vvv;
        }
        // s_* for next step are only rewritten after the next __syncthreads()
    }
}

// ---------------- groupnorm + silu gate (in-place on o) ----------------
// one block = one (b,t,h) row of DV=128
__global__ __launch_bounds__(128)
void post_kernel(float* __restrict__ o, const float* __restrict__ g,
                 const float* __restrict__ gnw)
{
    const int row = blockIdx.x;
    const int vv = threadIdx.x;
    const size_t idx = (size_t)row * DVV + vv;
    float val = o[idx];
    float sq = val * val;
#pragma unroll
    for (int off = 16; off > 0; off >>= 1)
        sq += __shfl_xor_sync(0xffffffff, sq, off);
    __shared__ float sw[4];
    if ((vv & 31) == 0) sw[vv >> 5] = sq;
    __syncthreads();
    float ms = (sw[0] + sw[1] + sw[2] + sw[3]) * (1.f / 128.f);
    float gv = g[idx];
    float sig = 1.f / (1.f + expf(-gv));
    o[idx] = val * rsqrtf(ms + 1e-5f) * gnw[vv] * gv * sig;
}

// ---------------- launch ----------------
extern "C" void kernel_launch(void* const* d_in, const int* in_sizes, int n_in,
                              void* d_out, int out_size)
{
    const float* x        = (const float*)d_in[0];
    const float* W_r      = (const float*)d_in[1];
    const float* mu_r     = (const float*)d_in[2];
    const float* W_k      = (const float*)d_in[3];
    const float* mu_k     = (const float*)d_in[4];
    const float* W_v      = (const float*)d_in[5];
    const float* mu_v     = (const float*)d_in[6];
    const float* W_g      = (const float*)d_in[7];
    const float* mu_g     = (const float*)d_in[8];
    const float* dd_mu    = (const float*)d_in[9];
    const float* dd_W1    = (const float*)d_in[10];
    const float* dd_W2    = (const float*)d_in[11];
    const float* dd_lamda = (const float*)d_in[12];
    const float* w_W1     = (const float*)d_in[13];
    const float* w_W2     = (const float*)d_in[14];
    const float* w_lamda  = (const float*)d_in[15];
    const float* bonus    = (const float*)d_in[16];
    const float* W_o      = (const float*)d_in[17];
    const float* g_norm_w = (const float*)d_in[18];
    float* out = (float*)d_out;

    float *rP, *kP, *vP, *gP, *wP, *xwP, *h1P, *h2P, *oP;
    cudaGetSymbolAddress((void**)&rP,  g_r);
    cudaGetSymbolAddress((void**)&kP,  g_k);
    cudaGetSymbolAddress((void**)&vP,  g_v);
    cudaGetSymbolAddress((void**)&gP,  g_g);
    cudaGetSymbolAddress((void**)&wP,  g_w);
    cudaGetSymbolAddress((void**)&xwP, g_xw);
    cudaGetSymbolAddress((void**)&h1P, g_h1);
    cudaGetSymbolAddress((void**)&h2P, g_h2);
    cudaGetSymbolAddress((void**)&oP,  g_o);

    const dim3 blk(256);
    const dim3 gridMy(1, MM / GBM);                 // N=32
    const dim3 gridK(KK / GBN, MM / GBM);           // N=1024
    const dim3 gridV(VV / GBN, MM / GBM);           // N=2048

    // w-path (LoRA chains)
    gemm_kernel<1, 1><<<gridMy, blk>>>(x,   dd_W1, h1P, MM, 32,  DD, dd_mu, nullptr,  nullptr);
    gemm_kernel<0, 2><<<gridK,  blk>>>(h1P, dd_W2, xwP, MM, DD,  32, nullptr, dd_lamda, x);
    gemm_kernel<0, 1><<<gridMy, blk>>>(xwP, w_W1,  h2P, MM, 32,  DD, nullptr, nullptr,  nullptr);
    gemm_kernel<0, 3><<<gridK,  blk>>>(h2P, w_W2,  wP,  MM, KK,  32, nullptr, w_lamda,  nullptr);

    // projections (token-shift modulation fused into A loader)
    gemm_kernel<1, 0><<<gridK, blk>>>(x, W_r, rP, MM, KK, DD, mu_r, nullptr, nullptr);
    gemm_kernel<1, 0><<<gridK, blk>>>(x, W_k, kP, MM, KK, DD, mu_k, nullptr, nullptr);
    gemm_kernel<1, 0><<<gridV, blk>>>(x, W_v, vP, MM, VV, DD, mu_v, nullptr, nullptr);
    gemm_kernel<1, 0><<<gridV, blk>>>(x, W_g, gP, MM, VV, DD, mu_g, nullptr, nullptr);

    // recurrence
    scan_kernel<<<BB * HH, 256>>>(rP, kP, vP, wP, bonus, oP);

    // groupnorm + silu gate (in place)
    post_kernel<<<MM * HH, 128>>>(oP, gP, g_norm_w);

    // output projection
    gemm_kernel<0, 0><<<gridK, blk>>>(oP, W_o, out, MM, DD, VV, nullptr, nullptr, nullptr);
}

// round 5
// speedup vs baseline: 1.6401x; 1.6401x over previous
#include <cuda_runtime.h>
#include <cuda_bf16.h>
#include <cstdint>

#define BB 4
#define TT 2048
#define DD 1024
#define HH 16
#define DKK 64
#define DVV 128
#define KK 1024
#define VV 2048
#define MM 8192

typedef __nv_bfloat16 bf16;

// ---------------- scratch (device globals; no allocation) ----------------
__device__ float g_r [(size_t)MM*KK];
__device__ float g_k [(size_t)MM*KK];
__device__ float g_w [(size_t)MM*KK];
__device__ float g_xw[(size_t)MM*DD];
__device__ float g_v [(size_t)MM*VV];
__device__ float g_g [(size_t)MM*VV];
__device__ float g_o [(size_t)MM*VV];
__device__ float g_h1[(size_t)MM*32];
__device__ float g_h2[(size_t)MM*32];

__device__ bf16 g_xh[4][(size_t)MM*DD];   // modulated x planes (r,k,v,g) hi
__device__ bf16 g_xl[4][(size_t)MM*DD];   // lo
__device__ bf16 g_oh[(size_t)MM*VV], g_ol[(size_t)MM*VV];
__device__ bf16 g_wrh[(size_t)KK*DD], g_wrl[(size_t)KK*DD];
__device__ bf16 g_wkh[(size_t)KK*DD], g_wkl[(size_t)KK*DD];
__device__ bf16 g_wvh[(size_t)VV*DD], g_wvl[(size_t)VV*DD];
__device__ bf16 g_wgh[(size_t)VV*DD], g_wgl[(size_t)VV*DD];
__device__ bf16 g_woh[(size_t)DD*VV], g_wol[(size_t)DD*VV];

// ---------------- helpers ----------------
__device__ __forceinline__ uint32_t smem_u32(const void* p){
    uint32_t a;
    asm("{ .reg .u64 t; cvta.to.shared.u64 t, %1; cvt.u32.u64 %0, t; }" : "=r"(a) : "l"(p));
    return a;
}
__device__ __forceinline__ void split_bf16(float a, unsigned short& h, unsigned short& l){
    bf16 bh = __float2bfloat16(a);
    bf16 bl = __float2bfloat16(a - __bfloat162float(bh));
    h = *(unsigned short*)&bh; l = *(unsigned short*)&bl;
}

#define CP_ASYNC16(dst, src) \
    asm volatile("cp.async.cg.shared.global [%0], [%1], 16;" :: "r"(dst), "l"(src))
#define CP_COMMIT() asm volatile("cp.async.commit_group;")
#define CP_WAIT2()  asm volatile("cp.async.wait_group 2;" ::: "memory")

#define LDMX4(r0,r1,r2,r3,a) \
    asm volatile("ldmatrix.sync.aligned.m8n8.x4.shared.b16 {%0,%1,%2,%3}, [%4];" \
        : "=r"(r0), "=r"(r1), "=r"(r2), "=r"(r3) : "r"(a))

#define MMA16816(c0,c1,c2,c3,a0,a1,a2,a3,b0,b1) \
    asm volatile("mma.sync.aligned.m16n8k16.row.col.f32.bf16.bf16.f32 " \
        "{%0,%1,%2,%3}, {%4,%5,%6,%7}, {%8,%9}, {%0,%1,%2,%3};" \
        : "+f"(c0), "+f"(c1), "+f"(c2), "+f"(c3) \
        : "r"(a0), "r"(a1), "r"(a2), "r"(a3), "r"(b0), "r"(b1))

// smem tile layout per plane: [128 rows][32 bf16] = 64B rows, XOR swizzle
__device__ __forceinline__ uint32_t swz(int row, int seg){
    return (uint32_t)(row*64 + ((seg ^ ((row>>1)&3))<<4));
}

// ---------------- prep: modulated x -> 4 x (hi,lo) bf16 planes ----------------
__global__ __launch_bounds__(256)
void prep_x(const float* __restrict__ x,
            const float* __restrict__ mur, const float* __restrict__ muk,
            const float* __restrict__ muv, const float* __restrict__ mug)
{
    const int i4 = blockIdx.x * 256 + threadIdx.x;
    const int row = i4 / (DD/4), c4 = i4 % (DD/4);
    const float4 xv = *(const float4*)(x + (size_t)row*DD + c4*4);
    float4 pv;
    if ((row & (TT-1)) == 0) pv = make_float4(0.f,0.f,0.f,0.f);
    else pv = *(const float4*)(x + (size_t)(row-1)*DD + c4*4);
    const float xb[4] = {xv.x, xv.y, xv.z, xv.w};
    const float dx[4] = {pv.x-xv.x, pv.y-xv.y, pv.z-xv.z, pv.w-xv.w};
    const float* mus[4] = {mur, muk, muv, mug};
    const size_t off = (size_t)row*DD + c4*4;
#pragma unroll
    for (int v = 0; v < 4; v++) {
        const float4 m = *(const float4*)(mus[v] + c4*4);
        const float mm[4] = {m.x, m.y, m.z, m.w};
        unsigned short hs[4], ls[4];
#pragma unroll
        for (int j = 0; j < 4; j++) split_bf16(xb[j] + dx[j]*mm[j], hs[j], ls[j]);
        uint2 H, L;
        H.x = hs[0] | ((uint32_t)hs[1]<<16); H.y = hs[2] | ((uint32_t)hs[3]<<16);
        L.x = ls[0] | ((uint32_t)ls[1]<<16); L.y = ls[2] | ((uint32_t)ls[3]<<16);
        *(uint2*)(&g_xh[v][off]) = H;
        *(uint2*)(&g_xl[v][off]) = L;
    }
}

// ---------------- prep: W[Kd][N] -> Wt[N][Kd] hi/lo planes ----------------
__global__ void prep_wT(const float* __restrict__ W, bf16* __restrict__ Wh,
                        bf16* __restrict__ Wl, int Kd, int N)
{
    __shared__ float t[32][33];
    const int x = blockIdx.x*32 + threadIdx.x;   // N index
    const int y0 = blockIdx.y*32;                // Kd index
    for (int j = threadIdx.y; j < 32; j += 8)
        t[j][threadIdx.x] = W[(size_t)(y0+j)*N + x];
    __syncthreads();
    const int ox = y0 + threadIdx.x;
    const int oy0 = blockIdx.x*32;
    for (int j = threadIdx.y; j < 32; j += 8) {
        unsigned short h, l;
        split_bf16(t[threadIdx.x][j], h, l);
        Wh[(size_t)(oy0+j)*Kd + ox] = *(bf16*)&h;
        Wl[(size_t)(oy0+j)*Kd + ox] = *(bf16*)&l;
    }
}

// ---------------- HMMA split-bf16 GEMM: C[M,N] = A @ W ----------------
// A planes [M][Kd] bf16 row-major; B planes [N][Kd] bf16 (W^T). M,N mult of 128.
#define STAGES 4
#define PLANE_BYTES 8192            // 128 x 32 bf16
#define CHUNK_BYTES (4*PLANE_BYTES) // Ah, Al, Bh, Bl
#define MMA_SMEM (STAGES*CHUNK_BYTES)

__global__ __launch_bounds__(256, 1)
void gemm_mma(const bf16* __restrict__ Ah, const bf16* __restrict__ Al,
              const bf16* __restrict__ Bh, const bf16* __restrict__ Bl,
              float* __restrict__ C, int N, int Kd)
{
    extern __shared__ char smem[];
    const uint32_t sb = smem_u32(smem);
    const int tid = threadIdx.x, lane = tid & 31, wid = tid >> 5;
    const int m0 = blockIdx.y * 128, n0 = blockIdx.x * 128;
    const int wm = (wid & 3) * 32, wn = (wid >> 2) * 64;
    const int NC = Kd >> 5;

    // cp.async assignment: per plane this thread copies items tid and tid+256
    // item -> row = item>>2 (0..127), seg = item&3 (16B segment within 64B row)
    const int r0_ = tid >> 2, s0_ = tid & 3;
    const int r1_ = r0_ + 64;
    const uint32_t d0 = swz(r0_, s0_), d1 = swz(r1_, s0_);
    const bf16* gsrc0[4] = {
        Ah + (size_t)(m0 + r0_)*Kd + s0_*8,
        Al + (size_t)(m0 + r0_)*Kd + s0_*8,
        Bh + (size_t)(n0 + r0_)*Kd + s0_*8,
        Bl + (size_t)(n0 + r0_)*Kd + s0_*8 };
    const bf16* gsrc1[4] = {
        Ah + (size_t)(m0 + r1_)*Kd + s0_*8,
        Al + (size_t)(m0 + r1_)*Kd + s0_*8,
        Bh + (size_t)(n0 + r1_)*Kd + s0_*8,
        Bl + (size_t)(n0 + r1_)*Kd + s0_*8 };

    auto issue = [&](int c){
        const uint32_t bb = sb + (c & (STAGES-1)) * CHUNK_BYTES;
        const int k0 = c * 32;
#pragma unroll
        for (int p = 0; p < 4; p++) {
            CP_ASYNC16(bb + p*PLANE_BYTES + d0, gsrc0[p] + k0);
            CP_ASYNC16(bb + p*PLANE_BYTES + d1, gsrc1[p] + k0);
        }
        CP_COMMIT();
    };

    float acc[2][8][4];
#pragma unroll
    for (int mt = 0; mt < 2; mt++)
#pragma unroll
        for (int nt = 0; nt < 8; nt++)
#pragma unroll
            for (int q = 0; q < 4; q++) acc[mt][nt][q] = 0.f;

    issue(0); issue(1); issue(2);

    // ldmatrix address components (within a plane tile)
    const int a_row = wm + (lane & 15);          // + mt*16
    const int a_s   = lane >> 4;                 // + 2s
    const int b_row = wn + (lane & 7) + ((lane >> 4) << 3);  // + nt2*16
    const int b_s   = (lane >> 3) & 1;           // + 2s

    for (int c = 0; c < NC; c++) {
        CP_WAIT2();
        __syncthreads();
        if (c + 3 < NC) issue(c + 3);
        const uint32_t bb = sb + (c & (STAGES-1)) * CHUNK_BYTES;

#pragma unroll
        for (int s = 0; s < 2; s++) {
            uint32_t afh[2][4], afl[2][4];
#pragma unroll
            for (int mt = 0; mt < 2; mt++) {
                uint32_t ad = swz(a_row + mt*16, 2*s + a_s);
                LDMX4(afh[mt][0], afh[mt][1], afh[mt][2], afh[mt][3], bb + 0*PLANE_BYTES + ad);
                LDMX4(afl[mt][0], afl[mt][1], afl[mt][2], afl[mt][3], bb + 1*PLANE_BYTES + ad);
            }
            uint32_t bfh[8][2], bfl[8][2];
#pragma unroll
            for (int nt2 = 0; nt2 < 4; nt2++) {
                uint32_t bd = swz(b_row + nt2*16, 2*s + b_s);
                LDMX4(bfh[2*nt2][0], bfh[2*nt2][1], bfh[2*nt2+1][0], bfh[2*nt2+1][1],
                      bb + 2*PLANE_BYTES + bd);
                LDMX4(bfl[2*nt2][0], bfl[2*nt2][1], bfl[2*nt2+1][0], bfl[2*nt2+1][1],
                      bb + 3*PLANE_BYTES + bd);
            }
#pragma unroll
            for (int mt = 0; mt < 2; mt++)
#pragma unroll
                for (int nt = 0; nt < 8; nt++) {
                    float* a_ = acc[mt][nt];
                    MMA16816(a_[0], a_[1], a_[2], a_[3],
                             afh[mt][0], afh[mt][1], afh[mt][2], afh[mt][3],
                             bfh[nt][0], bfh[nt][1]);
                    MMA16816(a_[0], a_[1], a_[2], a_[3],
                             afl[mt][0], afl[mt][1], afl[mt][2], afl[mt][3],
                             bfh[nt][0], bfh[nt][1]);
                    MMA16816(a_[0], a_[1], a_[2], a_[3],
                             afh[mt][0], afh[mt][1], afh[mt][2], afh[mt][3],
                             bfl[nt][0], bfl[nt][1]);
                }
        }
        __syncthreads();
    }

    // epilogue
#pragma unroll
    for (int mt = 0; mt < 2; mt++) {
        const int row = m0 + wm + mt*16 + (lane >> 2);
#pragma unroll
        for (int nt = 0; nt < 8; nt++) {
            const int col = n0 + wn + nt*8 + (lane & 3)*2;
            float2 v0 = make_float2(acc[mt][nt][0], acc[mt][nt][1]);
            float2 v1 = make_float2(acc[mt][nt][2], acc[mt][nt][3]);
            *(float2*)&C[(size_t)row*N + col]     = v0;
            *(float2*)&C[(size_t)(row+8)*N + col] = v1;
        }
    }
}

// ---------------- SIMT GEMM (LoRA path only) ----------------
#define GBM 128
#define GBN 128
#define GBK 8
template<int AMODE, int EPI>
__global__ __launch_bounds__(256)
void gemm_kernel(const float* __restrict__ A, const float* __restrict__ B,
                 float* __restrict__ C, int M, int N, int Kd,
                 const float* __restrict__ mu, const float* __restrict__ bias,
                 const float* __restrict__ X)
{
    __shared__ float As[GBK][GBM];
    __shared__ float Bs[GBK][GBN + 4];
    const int tid = threadIdx.x;
    const int tx = tid & 15, ty = tid >> 4;
    const int rowA = tid >> 1, colA = (tid & 1) * 4;
    const int rowB = tid >> 5, colB = (tid & 31) * 4;
    const int gRowA = blockIdx.y * GBM + rowA;
    const bool isT0 = ((gRowA & (TT - 1)) == 0);
    float acc[8][8];
#pragma unroll
    for (int i = 0; i < 8; i++)
#pragma unroll
        for (int j = 0; j < 8; j++) acc[i][j] = 0.f;
    const int gnB = blockIdx.x * GBN + colB;
    for (int k0 = 0; k0 < Kd; k0 += GBK) {
        const float* aptr = A + (size_t)gRowA * Kd + (k0 + colA);
        float4 a = *(const float4*)aptr;
        if (AMODE == 1) {
            float4 p;
            if (isT0) { p.x = p.y = p.z = p.w = 0.f; }
            else      { p = *(const float4*)(aptr - Kd); }
            float4 m4 = *(const float4*)(mu + k0 + colA);
            a.x += (p.x - a.x) * m4.x; a.y += (p.y - a.y) * m4.y;
            a.z += (p.z - a.z) * m4.z; a.w += (p.w - a.w) * m4.w;
        }
        As[colA+0][rowA] = a.x; As[colA+1][rowA] = a.y;
        As[colA+2][rowA] = a.z; As[colA+3][rowA] = a.w;
        float4 b;
        if (gnB < N) b = *(const float4*)(B + (size_t)(k0 + rowB) * N + gnB);
        else { b.x = b.y = b.z = b.w = 0.f; }
        *(float4*)&Bs[rowB][colB] = b;
        __syncthreads();
#pragma unroll
        for (int kk = 0; kk < GBK; ++kk) {
            float ra[8], rb[8];
            *(float4*)&ra[0] = *(const float4*)&As[kk][ty*8];
            *(float4*)&ra[4] = *(const float4*)&As[kk][ty*8+4];
            *(float4*)&rb[0] = *(const float4*)&Bs[kk][tx*8];
            *(float4*)&rb[4] = *(const float4*)&Bs[kk][tx*8+4];
#pragma unroll
            for (int i = 0; i < 8; i++)
#pragma unroll
                for (int j = 0; j < 8; j++) acc[i][j] += ra[i] * rb[j];
        }
        __syncthreads();
    }
#pragma unroll
    for (int i = 0; i < 8; i++) {
        const int r = blockIdx.y * GBM + ty*8 + i;
        const bool rT0 = ((r & (TT - 1)) == 0);
#pragma unroll
        for (int j = 0; j < 8; j++) {
            const int col = blockIdx.x * GBN + tx*8 + j;
            if (col >= N) continue;
            const size_t cidx = (size_t)r * N + col;
            float vacc = acc[i][j];
            if (EPI == 0) C[cidx] = vacc;
            else if (EPI == 1) C[cidx] = tanhf(vacc);
            else if (EPI == 2) {
                float lam = vacc + bias[col];
                float xv = X[cidx];
                float xp = rT0 ? 0.f : X[cidx - N];
                C[cidx] = xv + (xp - xv) * lam;
            } else C[cidx] = -expf(vacc + bias[col]);
        }
    }
}

// ---------------- recurrent scan ----------------
__global__ __launch_bounds__(256)
void scan_kernel(const float* __restrict__ r, const float* __restrict__ k,
                 const float* __restrict__ v, const float* __restrict__ w,
                 const float* __restrict__ bonus, float* __restrict__ o)
{
    const int bh = blockIdx.x;
    const int b = bh / HH, hh = bh % HH;
    const int tid = threadIdx.x;
    const int vv = tid & 127, half = tid >> 7, kbase = half * 32;
    __shared__ float s_r[DKK], s_k[DKK], s_ew[DKK];
    __shared__ float s_v[DVV], s_part[DVV];
    __shared__ float s_u[DKK];
    __shared__ float s_dp[2];
    if (tid < DKK) s_u[tid] = bonus[hh * DKK + tid];
    __syncthreads();
    float h[32];
#pragma unroll
    for (int i = 0; i < 32; i++) h[i] = 0.f;
    const size_t rb = (size_t)(b * TT) * KK + hh * DKK;
    const size_t vb = (size_t)(b * TT) * VV + hh * DVV;
    for (int t = 0; t < TT; ++t) {
        const size_t ro = rb + (size_t)t * KK;
        const size_t vo = vb + (size_t)t * VV;
        if (tid < DKK) {
            float kv_ = k[ro + tid], rv_ = r[ro + tid];
            float uk_ = s_u[tid] * kv_;
            s_r[tid] = rv_; s_k[tid] = kv_;
            s_ew[tid] = expf(w[ro + tid]);
            float dp = rv_ * uk_;
#pragma unroll
            for (int off = 16; off > 0; off >>= 1)
                dp += __shfl_xor_sync(0xffffffff, dp, off);
            if ((tid & 31) == 0) s_dp[tid >> 5] = dp;
        }
        if (tid >= 128) s_v[tid - 128] = v[vo + (tid - 128)];
        __syncthreads();
        const float vvv = s_v[vv];
        float accp = 0.f;
#pragma unroll
        for (int i = 0; i < 32; i++) {
            const int kkk = kbase + i;
            const float hv = h[i];
            accp += s_r[kkk] * hv;
            h[i] = hv * s_ew[kkk] + s_k[kkk] * vvv;
        }
        if (half == 1) s_part[vv] = accp;
        __syncthreads();
        if (half == 0) {
            const float d = s_dp[0] + s_dp[1];
            o[vo + vv] = accp + s_part[vv] + d * vvv;
        }
    }
}

// ---------------- groupnorm + silu gate -> o hi/lo planes ----------------
__global__ __launch_bounds__(128)
void post_kernel(const float* __restrict__ o, const float* __restrict__ g,
                 const float* __restrict__ gnw)
{
    const int row = blockIdx.x;
    const int vv = threadIdx.x;
    const size_t idx = (size_t)row * DVV + vv;
    float val = o[idx];
    float sq = val * val;
#pragma unroll
    for (int off = 16; off > 0; off >>= 1)
        sq += __shfl_xor_sync(0xffffffff, sq, off);
    __shared__ float sw[4];
    if ((vv & 31) == 0) sw[vv >> 5] = sq;
    __syncthreads();
    float ms = (sw[0] + sw[1] + sw[2] + sw[3]) * (1.f / 128.f);
    float gv = g[idx];
    float sig = 1.f / (1.f + expf(-gv));
    float res = val * rsqrtf(ms + 1e-5f) * gnw[vv] * gv * sig;
    unsigned short h, l;
    split_bf16(res, h, l);
    g_oh[idx] = *(bf16*)&h;
    g_ol[idx] = *(bf16*)&l;
}

// ---------------- launch ----------------
extern "C" void kernel_launch(void* const* d_in, const int* in_sizes, int n_in,
                              void* d_out, int out_size)
{
    const float* x        = (const float*)d_in[0];
    const float* W_r      = (const float*)d_in[1];
    const float* mu_r     = (const float*)d_in[2];
    const float* W_k      = (const float*)d_in[3];
    const float* mu_k     = (const float*)d_in[4];
    const float* W_v      = (const float*)d_in[5];
    const float* mu_v     = (const float*)d_in[6];
    const float* W_g      = (const float*)d_in[7];
    const float* mu_g     = (const float*)d_in[8];
    const float* dd_mu    = (const float*)d_in[9];
    const float* dd_W1    = (const float*)d_in[10];
    const float* dd_W2    = (const float*)d_in[11];
    const float* dd_lamda = (const float*)d_in[12];
    const float* w_W1     = (const float*)d_in[13];
    const float* w_W2     = (const float*)d_in[14];
    const float* w_lamda  = (const float*)d_in[15];
    const float* bonus    = (const float*)d_in[16];
    const float* W_o      = (const float*)d_in[17];
    const float* g_norm_w = (const float*)d_in[18];
    float* out = (float*)d_out;

    float *rP,*kP,*vP,*gP,*wP,*xwP,*h1P,*h2P,*oP;
    cudaGetSymbolAddress((void**)&rP,  g_r);
    cudaGetSymbolAddress((void**)&kP,  g_k);
    cudaGetSymbolAddress((void**)&vP,  g_v);
    cudaGetSymbolAddress((void**)&gP,  g_g);
    cudaGetSymbolAddress((void**)&wP,  g_w);
    cudaGetSymbolAddress((void**)&xwP, g_xw);
    cudaGetSymbolAddress((void**)&h1P, g_h1);
    cudaGetSymbolAddress((void**)&h2P, g_h2);
    cudaGetSymbolAddress((void**)&oP,  g_o);

    bf16 *xhP,*xlP,*ohP,*olP;
    bf16 *wrh,*wrl,*wkh,*wkl,*wvh,*wvl,*wgh,*wgl,*woh,*wol;
    cudaGetSymbolAddress((void**)&xhP, g_xh);
    cudaGetSymbolAddress((void**)&xlP, g_xl);
    cudaGetSymbolAddress((void**)&ohP, g_oh);
    cudaGetSymbolAddress((void**)&olP, g_ol);
    cudaGetSymbolAddress((void**)&wrh, g_wrh); cudaGetSymbolAddress((void**)&wrl, g_wrl);
    cudaGetSymbolAddress((void**)&wkh, g_wkh); cudaGetSymbolAddress((void**)&wkl, g_wkl);
    cudaGetSymbolAddress((void**)&wvh, g_wvh); cudaGetSymbolAddress((void**)&wvl, g_wvl);
    cudaGetSymbolAddress((void**)&wgh, g_wgh); cudaGetSymbolAddress((void**)&wgl, g_wgl);
    cudaGetSymbolAddress((void**)&woh, g_woh); cudaGetSymbolAddress((void**)&wol, g_wol);
    const size_t PL = (size_t)MM * DD;

    cudaFuncSetAttribute(gemm_mma, cudaFuncAttributeMaxDynamicSharedMemorySize, MMA_SMEM);

    const dim3 blk(256);
    // prep planes
    prep_x<<<(MM*DD/4)/256, 256>>>(x, mu_r, mu_k, mu_v, mu_g);
    prep_wT<<<dim3(KK/32, DD/32), dim3(32,8)>>>(W_r, wrh, wrl, DD, KK);
    prep_wT<<<dim3(KK/32, DD/32), dim3(32,8)>>>(W_k, wkh, wkl, DD, KK);
    prep_wT<<<dim3(VV/32, DD/32), dim3(32,8)>>>(W_v, wvh, wvl, DD, VV);
    prep_wT<<<dim3(VV/32, DD/32), dim3(32,8)>>>(W_g, wgh, wgl, DD, VV);
    prep_wT<<<dim3(DD/32, VV/32), dim3(32,8)>>>(W_o, woh, wol, VV, DD);

    // LoRA chains (SIMT fp32, exact)
    gemm_kernel<1,1><<<dim3(1, MM/GBM),  blk>>>(x,   dd_W1, h1P, MM, 32,  DD, dd_mu, nullptr,  nullptr);
    gemm_kernel<0,2><<<dim3(KK/GBN, MM/GBM), blk>>>(h1P, dd_W2, xwP, MM, DD,  32, nullptr, dd_lamda, x);
    gemm_kernel<0,1><<<dim3(1, MM/GBM),  blk>>>(xwP, w_W1,  h2P, MM, 32,  DD, nullptr, nullptr,  nullptr);
    gemm_kernel<0,3><<<dim3(KK/GBN, MM/GBM), blk>>>(h2P, w_W2,  wP,  MM, KK,  32, nullptr, w_lamda,  nullptr);

    // projections on HMMA tensor path (split-bf16, 3 products)
    gemm_mma<<<dim3(KK/128, MM/128), blk, MMA_SMEM>>>(xhP+0*PL, xlP+0*PL, wrh, wrl, rP, KK, DD);
    gemm_mma<<<dim3(KK/128, MM/128), blk, MMA_SMEM>>>(xhP+1*PL, xlP+1*PL, wkh, wkl, kP, KK, DD);
    gemm_mma<<<dim3(VV/128, MM/128), blk, MMA_SMEM>>>(xhP+2*PL, xlP+2*PL, wvh, wvl, vP, VV, DD);
    gemm_mma<<<dim3(VV/128, MM/128), blk, MMA_SMEM>>>(xhP+3*PL, xlP+3*PL, wgh, wgl, gP, VV, DD);

    // recurrence
    scan_kernel<<<BB*HH, 256>>>(rP, kP, vP, wP, bonus, oP);

    // groupnorm + silu gate -> o planes
    post_kernel<<<MM*HH, 128>>>(oP, gP, g_norm_w);

    // output projection on HMMA tensor path
    gemm_mma<<<dim3(DD/128, MM/128), blk, MMA_SMEM>>>(ohP, olP, woh, wol, out, DD, VV);
}

// round 6
// speedup vs baseline: 2.2899x; 1.3962x over previous
#include <cuda_runtime.h>
#include <cuda_bf16.h>
#include <cstdint>

#define BB 4
#define TT 2048
#define DD 1024
#define HH 16
#define DKK 64
#define DVV 128
#define KK 1024
#define VV 2048
#define MM 8192

typedef __nv_bfloat16 bf16;

// ---------------- scratch (device globals; no allocation) ----------------
__device__ float g_r [(size_t)MM*KK];
__device__ float g_k [(size_t)MM*KK];
__device__ float g_w [(size_t)MM*KK];
__device__ float g_xw[(size_t)MM*DD];
__device__ float g_v [(size_t)MM*VV];
__device__ float g_g [(size_t)MM*VV];
__device__ float g_o [(size_t)MM*VV];
__device__ float g_h1[(size_t)MM*32];
__device__ float g_h2[(size_t)MM*32];

__device__ bf16 g_xh[4][(size_t)MM*DD];   // modulated x planes (r,k,v,g) hi
__device__ bf16 g_xl[4][(size_t)MM*DD];   // lo
__device__ bf16 g_oh[(size_t)MM*VV], g_ol[(size_t)MM*VV];
__device__ bf16 g_wrh[(size_t)KK*DD], g_wrl[(size_t)KK*DD];
__device__ bf16 g_wkh[(size_t)KK*DD], g_wkl[(size_t)KK*DD];
__device__ bf16 g_wvh[(size_t)VV*DD], g_wvl[(size_t)VV*DD];
__device__ bf16 g_wgh[(size_t)VV*DD], g_wgl[(size_t)VV*DD];
__device__ bf16 g_woh[(size_t)DD*VV], g_wol[(size_t)DD*VV];

// ---------------- helpers ----------------
__device__ __forceinline__ uint32_t smem_u32(const void* p){
    uint32_t a;
    asm("{ .reg .u64 t; cvta.to.shared.u64 t, %1; cvt.u32.u64 %0, t; }" : "=r"(a) : "l"(p));
    return a;
}
__device__ __forceinline__ void split_bf16(float a, unsigned short& h, unsigned short& l){
    bf16 bh = __float2bfloat16(a);
    bf16 bl = __float2bfloat16(a - __bfloat162float(bh));
    h = *(unsigned short*)&bh; l = *(unsigned short*)&bl;
}

#define CP_ASYNC16(dst, src) \
    asm volatile("cp.async.cg.shared.global [%0], [%1], 16;" :: "r"(dst), "l"(src))
#define CP_COMMIT() asm volatile("cp.async.commit_group;")
#define CP_WAIT1()  asm volatile("cp.async.wait_group 1;" ::: "memory")

#define LDMX4(r0,r1,r2,r3,a) \
    asm volatile("ldmatrix.sync.aligned.m8n8.x4.shared.b16 {%0,%1,%2,%3}, [%4];" \
        : "=r"(r0), "=r"(r1), "=r"(r2), "=r"(r3) : "r"(a))

#define MMA16816(c0,c1,c2,c3,a0,a1,a2,a3,b0,b1) \
    asm volatile("mma.sync.aligned.m16n8k16.row.col.f32.bf16.bf16.f32 " \
        "{%0,%1,%2,%3}, {%4,%5,%6,%7}, {%8,%9}, {%0,%1,%2,%3};" \
        : "+f"(c0), "+f"(c1), "+f"(c2), "+f"(c3) \
        : "r"(a0), "r"(a1), "r"(a2), "r"(a3), "r"(b0), "r"(b1))

// smem tile layout per plane: [128 rows][32 bf16] = 64B rows, XOR swizzle
__device__ __forceinline__ uint32_t swz(int row, int seg){
    return (uint32_t)(row*64 + ((seg ^ ((row>>1)&3))<<4));
}

// ---------------- prep: modulated x -> 4 x (hi,lo) bf16 planes ----------------
__global__ __launch_bounds__(256)
void prep_x(const float* __restrict__ x,
            const float* __restrict__ mur, const float* __restrict__ muk,
            const float* __restrict__ muv, const float* __restrict__ mug)
{
    const int i4 = blockIdx.x * 256 + threadIdx.x;
    const int row = i4 / (DD/4), c4 = i4 % (DD/4);
    const float4 xv = *(const float4*)(x + (size_t)row*DD + c4*4);
    float4 pv;
    if ((row & (TT-1)) == 0) pv = make_float4(0.f,0.f,0.f,0.f);
    else pv = *(const float4*)(x + (size_t)(row-1)*DD + c4*4);
    const float xb[4] = {xv.x, xv.y, xv.z, xv.w};
    const float dx[4] = {pv.x-xv.x, pv.y-xv.y, pv.z-xv.z, pv.w-xv.w};
    const float* mus[4] = {mur, muk, muv, mug};
    const size_t off = (size_t)row*DD + c4*4;
#pragma unroll
    for (int v = 0; v < 4; v++) {
        const float4 m = *(const float4*)(mus[v] + c4*4);
        const float mm[4] = {m.x, m.y, m.z, m.w};
        unsigned short hs[4], ls[4];
#pragma unroll
        for (int j = 0; j < 4; j++) split_bf16(xb[j] + dx[j]*mm[j], hs[j], ls[j]);
        uint2 H, L;
        H.x = hs[0] | ((uint32_t)hs[1]<<16); H.y = hs[2] | ((uint32_t)hs[3]<<16);
        L.x = ls[0] | ((uint32_t)ls[1]<<16); L.y = ls[2] | ((uint32_t)ls[3]<<16);
        *(uint2*)(&g_xh[v][off]) = H;
        *(uint2*)(&g_xl[v][off]) = L;
    }
}

// ---------------- prep: W[Kd][N] -> Wt[N][Kd] hi/lo planes ----------------
__global__ void prep_wT(const float* __restrict__ W, bf16* __restrict__ Wh,
                        bf16* __restrict__ Wl, int Kd, int N)
{
    __shared__ float t[32][33];
    const int x = blockIdx.x*32 + threadIdx.x;   // N index
    const int y0 = blockIdx.y*32;                // Kd index
    for (int j = threadIdx.y; j < 32; j += 8)
        t[j][threadIdx.x] = W[(size_t)(y0+j)*N + x];
    __syncthreads();
    const int ox = y0 + threadIdx.x;
    const int oy0 = blockIdx.x*32;
    for (int j = threadIdx.y; j < 32; j += 8) {
        unsigned short h, l;
        split_bf16(t[threadIdx.x][j], h, l);
        Wh[(size_t)(oy0+j)*Kd + ox] = *(bf16*)&h;
        Wl[(size_t)(oy0+j)*Kd + ox] = *(bf16*)&l;
    }
}

// ---------------- HMMA split-bf16 GEMM: C[M,N] = A @ W ----------------
// A planes [M][Kd] bf16 row-major; B planes [N][Kd] bf16 (W^T). M,N mult of 128.
// 3-stage cp.async pipeline, 96KB smem -> 2 CTAs/SM.
#define STAGES 3
#define PLANE_BYTES 8192            // 128 x 32 bf16
#define CHUNK_BYTES (4*PLANE_BYTES) // Ah, Al, Bh, Bl
#define MMA_SMEM (STAGES*CHUNK_BYTES)

__global__ __launch_bounds__(256, 2)
void gemm_mma(const bf16* __restrict__ Ah, const bf16* __restrict__ Al,
              const bf16* __restrict__ Bh, const bf16* __restrict__ Bl,
              float* __restrict__ C, int N, int Kd)
{
    extern __shared__ char smem[];
    const uint32_t sb = smem_u32(smem);
    const int tid = threadIdx.x, lane = tid & 31, wid = tid >> 5;
    const int m0 = blockIdx.y * 128, n0 = blockIdx.x * 128;
    const int wm = (wid & 3) * 32, wn = (wid >> 2) * 64;
    const int NC = Kd >> 5;

    // cp.async: each thread copies 2 x 16B per plane (rows r0_, r0_+64)
    const int r0_ = tid >> 2, s0_ = tid & 3;
    const uint32_t d0 = swz(r0_, s0_), d1 = swz(r0_ + 64, s0_);
    const size_t rowoff = (size_t)64 * Kd;
    const bf16* gp[4] = {
        Ah + (size_t)(m0 + r0_)*Kd + s0_*8,
        Al + (size_t)(m0 + r0_)*Kd + s0_*8,
        Bh + (size_t)(n0 + r0_)*Kd + s0_*8,
        Bl + (size_t)(n0 + r0_)*Kd + s0_*8 };

    uint32_t bufis = 0;   // issue-side buffer index
    auto issue = [&](int c){
        const uint32_t bb = sb + bufis * CHUNK_BYTES;
        if (++bufis == STAGES) bufis = 0;
        const int k0 = c * 32;
#pragma unroll
        for (int p = 0; p < 4; p++) {
            CP_ASYNC16(bb + p*PLANE_BYTES + d0, gp[p] + k0);
            CP_ASYNC16(bb + p*PLANE_BYTES + d1, gp[p] + rowoff + k0);
        }
        CP_COMMIT();
    };

    float acc[2][8][4];
#pragma unroll
    for (int mt = 0; mt < 2; mt++)
#pragma unroll
        for (int nt = 0; nt < 8; nt++)
#pragma unroll
            for (int q = 0; q < 4; q++) acc[mt][nt][q] = 0.f;

    issue(0); issue(1);

    const int a_row = wm + (lane & 15);
    const int a_s   = lane >> 4;
    const int b_row = wn + (lane & 7) + ((lane >> 4) << 3);
    const int b_s   = (lane >> 3) & 1;

    uint32_t bufc = 0;   // compute-side buffer index
    for (int c = 0; c < NC; c++) {
        CP_WAIT1();
        __syncthreads();
        if (c + 2 < NC) issue(c + 2);
        const uint32_t bb = sb + bufc * CHUNK_BYTES;
        if (++bufc == STAGES) bufc = 0;

#pragma unroll
        for (int s = 0; s < 2; s++) {
            uint32_t afh[2][4], afl[2][4];
#pragma unroll
            for (int mt = 0; mt < 2; mt++) {
                uint32_t ad = swz(a_row + mt*16, 2*s + a_s);
                LDMX4(afh[mt][0], afh[mt][1], afh[mt][2], afh[mt][3], bb + 0*PLANE_BYTES + ad);
                LDMX4(afl[mt][0], afl[mt][1], afl[mt][2], afl[mt][3], bb + 1*PLANE_BYTES + ad);
            }
#pragma unroll
            for (int nt2 = 0; nt2 < 4; nt2++) {
                uint32_t bd = swz(b_row + nt2*16, 2*s + b_s);
                uint32_t bh0,bh1,bh2,bh3, bl0,bl1,bl2,bl3;
                LDMX4(bh0, bh1, bh2, bh3, bb + 2*PLANE_BYTES + bd);
                LDMX4(bl0, bl1, bl2, bl3, bb + 3*PLANE_BYTES + bd);
#pragma unroll
                for (int mt = 0; mt < 2; mt++) {
                    float* a0 = acc[mt][2*nt2];
                    float* a1 = acc[mt][2*nt2+1];
                    MMA16816(a0[0],a0[1],a0[2],a0[3],
                             afh[mt][0],afh[mt][1],afh[mt][2],afh[mt][3], bh0,bh1);
                    MMA16816(a0[0],a0[1],a0[2],a0[3],
                             afl[mt][0],afl[mt][1],afl[mt][2],afl[mt][3], bh0,bh1);
                    MMA16816(a0[0],a0[1],a0[2],a0[3],
                             afh[mt][0],afh[mt][1],afh[mt][2],afh[mt][3], bl0,bl1);
                    MMA16816(a1[0],a1[1],a1[2],a1[3],
                             afh[mt][0],afh[mt][1],afh[mt][2],afh[mt][3], bh2,bh3);
                    MMA16816(a1[0],a1[1],a1[2],a1[3],
                             afl[mt][0],afl[mt][1],afl[mt][2],afl[mt][3], bh2,bh3);
                    MMA16816(a1[0],a1[1],a1[2],a1[3],
                             afh[mt][0],afh[mt][1],afh[mt][2],afh[mt][3], bl2,bl3);
                }
            }
        }
    }

    // epilogue
#pragma unroll
    for (int mt = 0; mt < 2; mt++) {
        const int row = m0 + wm + mt*16 + (lane >> 2);
#pragma unroll
        for (int nt = 0; nt < 8; nt++) {
            const int col = n0 + wn + nt*8 + (lane & 3)*2;
            float2 v0 = make_float2(acc[mt][nt][0], acc[mt][nt][1]);
            float2 v1 = make_float2(acc[mt][nt][2], acc[mt][nt][3]);
            *(float2*)&C[(size_t)row*N + col]     = v0;
            *(float2*)&C[(size_t)(row+8)*N + col] = v1;
        }
    }
}

// ---------------- skinny GEMM: C[M,32] = tanh( Amod[M,Kd] @ W[Kd,32] ) ----------------
// AMODE 1: a = x + (x_prev - x)*mu[k]
__global__ __launch_bounds__(256)
void gemm_skinny(const float* __restrict__ A, const float* __restrict__ W,
                 float* __restrict__ C, int Kd,
                 const float* __restrict__ mu, int amode)
{
    __shared__ float As[32][132];
    __shared__ float Bs[32][36];
    const int tid = threadIdx.x;
    const int colg = (tid & 7) * 4;
    const int rowg = (tid >> 3) * 4;
    const int m0 = blockIdx.x * 128;
    float acc[4][4];
#pragma unroll
    for (int i = 0; i < 4; i++)
#pragma unroll
        for (int j = 0; j < 4; j++) acc[i][j] = 0.f;

    for (int k0 = 0; k0 < Kd; k0 += 32) {
        // A tile 128x32 (1024 float4 items: row=i>>3, c4=i&7)
#pragma unroll
        for (int q = 0; q < 4; q++) {
            const int i = tid + 256*q;
            const int row = i >> 3, c4 = i & 7;
            const float* aptr = A + (size_t)(m0+row)*Kd + k0 + c4*4;
            float4 a = *(const float4*)aptr;
            if (amode) {
                float4 p;
                if (((m0+row) & (TT-1)) == 0) { p.x=p.y=p.z=p.w=0.f; }
                else p = *(const float4*)(aptr - Kd);
                float4 m4 = *(const float4*)(mu + k0 + c4*4);
                a.x += (p.x - a.x)*m4.x; a.y += (p.y - a.y)*m4.y;
                a.z += (p.z - a.z)*m4.z; a.w += (p.w - a.w)*m4.w;
            }
            As[c4*4+0][row] = a.x; As[c4*4+1][row] = a.y;
            As[c4*4+2][row] = a.z; As[c4*4+3][row] = a.w;
        }
        // B tile 32x32 (256 float4 items: krow=tid>>3, c4=tid&7)
        {
            const int krow = tid >> 3, c4 = tid & 7;
            float4 b = *(const float4*)(W + (size_t)(k0+krow)*32 + c4*4);
            Bs[krow][c4*4+0] = b.x; Bs[krow][c4*4+1] = b.y;
            Bs[krow][c4*4+2] = b.z; Bs[krow][c4*4+3] = b.w;
        }
        __syncthreads();
#pragma unroll
        for (int kk = 0; kk < 32; kk++) {
            float a[4], b[4];
            *(float4*)a = *(const float4*)&As[kk][rowg];
            *(float4*)b = *(const float4*)&Bs[kk][colg];
#pragma unroll
            for (int i = 0; i < 4; i++)
#pragma unroll
                for (int j = 0; j < 4; j++) acc[i][j] += a[i] * b[j];
        }
        __syncthreads();
    }
#pragma unroll
    for (int i = 0; i < 4; i++)
#pragma unroll
        for (int j = 0; j < 4; j++)
            C[(size_t)(m0+rowg+i)*32 + colg + j] = tanhf(acc[i][j]);
}

// ---------------- SIMT GEMM (wide LoRA: Kd=32) ----------------
#define GBM 128
#define GBN 128
#define GBK 8
template<int EPI>   // 2 = xw-combine, 3 = -exp(+bias)
__global__ __launch_bounds__(256)
void gemm_wide(const float* __restrict__ A, const float* __restrict__ B,
               float* __restrict__ C, int N, int Kd,
               const float* __restrict__ bias, const float* __restrict__ X)
{
    __shared__ float As[GBK][GBM];
    __shared__ float Bs[GBK][GBN + 4];
    const int tid = threadIdx.x;
    const int tx = tid & 15, ty = tid >> 4;
    const int rowA = tid >> 1, colA = (tid & 1) * 4;
    const int rowB = tid >> 5, colB = (tid & 31) * 4;
    const int gRowA = blockIdx.y * GBM + rowA;
    float acc[8][8];
#pragma unroll
    for (int i = 0; i < 8; i++)
#pragma unroll
        for (int j = 0; j < 8; j++) acc[i][j] = 0.f;
    const int gnB = blockIdx.x * GBN + colB;
    for (int k0 = 0; k0 < Kd; k0 += GBK) {
        float4 a = *(const float4*)(A + (size_t)gRowA * Kd + (k0 + colA));
        As[colA+0][rowA] = a.x; As[colA+1][rowA] = a.y;
        As[colA+2][rowA] = a.z; As[colA+3][rowA] = a.w;
        float4 b = *(const float4*)(B + (size_t)(k0 + rowB) * N + gnB);
        *(float4*)&Bs[rowB][colB] = b;
        __syncthreads();
#pragma unroll
        for (int kk = 0; kk < GBK; ++kk) {
            float ra[8], rb[8];
            *(float4*)&ra[0] = *(const float4*)&As[kk][ty*8];
            *(float4*)&ra[4] = *(const float4*)&As[kk][ty*8+4];
            *(float4*)&rb[0] = *(const float4*)&Bs[kk][tx*8];
            *(float4*)&rb[4] = *(const float4*)&Bs[kk][tx*8+4];
#pragma unroll
            for (int i = 0; i < 8; i++)
#pragma unroll
                for (int j = 0; j < 8; j++) acc[i][j] += ra[i] * rb[j];
        }
        __syncthreads();
    }
#pragma unroll
    for (int i = 0; i < 8; i++) {
        const int r = blockIdx.y * GBM + ty*8 + i;
        const bool rT0 = ((r & (TT - 1)) == 0);
#pragma unroll
        for (int j = 0; j < 8; j++) {
            const int col = blockIdx.x * GBN + tx*8 + j;
            const size_t cidx = (size_t)r * N + col;
            float vacc = acc[i][j];
            if (EPI == 2) {
                float lam = vacc + bias[col];
                float xv = X[cidx];
                float xp = rT0 ? 0.f : X[cidx - N];
                C[cidx] = xv + (xp - xv) * lam;
            } else C[cidx] = -expf(vacc + bias[col]);
        }
    }
}

// ---------------- recurrent scan v2 ----------------
// 128 CTAs: (b,h,vhalf). 256 threads: kq = tid>>6 (k-quarter), vv = tid&63.
// State h[16] per thread. Software-pipelined global loads.
__global__ __launch_bounds__(256)
void scan_kernel(const float* __restrict__ r, const float* __restrict__ k,
                 const float* __restrict__ v, const float* __restrict__ w,
                 const float* __restrict__ bonus, float* __restrict__ o)
{
    const int cta = blockIdx.x;
    const int bh = cta >> 1, vhalf = cta & 1;
    const int b = bh / HH, hh = bh % HH;
    const int tid = threadIdx.x;
    const int kq = tid >> 6, vv = tid & 63;
    const int kbase = kq * 16;

    __shared__ float s_r[DKK], s_k[DKK], s_ew[DKK];
    __shared__ float s_v[64];
    __shared__ float s_part[4][64];
    __shared__ float s_dp[2];

    const size_t rb = (size_t)(b * TT) * KK + hh * DKK;
    const size_t vb = (size_t)(b * TT) * VV + hh * DVV + vhalf * 64;

    float h[16];
#pragma unroll
    for (int i = 0; i < 16; i++) h[i] = 0.f;

    float p_r = 0.f, p_k = 0.f, p_w = 0.f, p_u = 0.f, p_v = 0.f;
    if (tid < 64) {
        p_u = bonus[hh * DKK + tid];
        p_r = r[rb + tid]; p_k = k[rb + tid]; p_w = w[rb + tid];
    } else if (tid < 128) {
        p_v = v[vb + (tid - 64)];
    }

    for (int t = 0; t < TT; ++t) {
        if (tid < 64) {
            s_r[tid] = p_r; s_k[tid] = p_k; s_ew[tid] = expf(p_w);
            float dp = p_r * p_u * p_k;
#pragma unroll
            for (int off = 16; off > 0; off >>= 1)
                dp += __shfl_xor_sync(0xffffffff, dp, off);
            if ((tid & 31) == 0) s_dp[tid >> 5] = dp;
        } else if (tid < 128) {
            s_v[tid - 64] = p_v;
        }
        __syncthreads();
        if (t + 1 < TT) {
            const size_t ro2 = rb + (size_t)(t+1) * KK;
            if (tid < 64) { p_r = r[ro2 + tid]; p_k = k[ro2 + tid]; p_w = w[ro2 + tid]; }
            else if (tid < 128) p_v = v[vb + (size_t)(t+1) * VV + (tid - 64)];
        }
        const float vvv = s_v[vv];
        float accp = 0.f;
#pragma unroll
        for (int i4 = 0; i4 < 4; i4++) {
            float4 r4 = *(const float4*)&s_r[kbase + i4*4];
            float4 k4 = *(const float4*)&s_k[kbase + i4*4];
            float4 e4 = *(const float4*)&s_ew[kbase + i4*4];
            float* hp = &h[i4*4];
            accp += r4.x*hp[0]; hp[0] = hp[0]*e4.x + k4.x*vvv;
            accp += r4.y*hp[1]; hp[1] = hp[1]*e4.y + k4.y*vvv;
            accp += r4.z*hp[2]; hp[2] = hp[2]*e4.z + k4.z*vvv;
            accp += r4.w*hp[3]; hp[3] = hp[3]*e4.w + k4.w*vvv;
        }
        s_part[kq][vv] = accp;
        __syncthreads();
        if (kq == 0) {
            const float d = s_dp[0] + s_dp[1];
            o[vb + (size_t)t*VV + vv] =
                accp + s_part[1][vv] + s_part[2][vv] + s_part[3][vv] + d * vvv;
        }
    }
}

// ---------------- groupnorm + silu gate -> o hi/lo planes ----------------
__global__ __launch_bounds__(128)
void post_kernel(const float* __restrict__ o, const float* __restrict__ g,
                 const float* __restrict__ gnw)
{
    const int row = blockIdx.x;
    const int vv = threadIdx.x;
    const size_t idx = (size_t)row * DVV + vv;
    float val = o[idx];
    float sq = val * val;
#pragma unroll
    for (int off = 16; off > 0; off >>= 1)
        sq += __shfl_xor_sync(0xffffffff, sq, off);
    __shared__ float sw[4];
    if ((vv & 31) == 0) sw[vv >> 5] = sq;
    __syncthreads();
    float ms = (sw[0] + sw[1] + sw[2] + sw[3]) * (1.f / 128.f);
    float gv = g[idx];
    float sig = 1.f / (1.f + expf(-gv));
    float res = val * rsqrtf(ms + 1e-5f) * gnw[vv] * gv * sig;
    unsigned short h, l;
    split_bf16(res, h, l);
    g_oh[idx] = *(bf16*)&h;
    g_ol[idx] = *(bf16*)&l;
}

// ---------------- launch ----------------
extern "C" void kernel_launch(void* const* d_in, const int* in_sizes, int n_in,
                              void* d_out, int out_size)
{
    const float* x        = (const float*)d_in[0];
    const float* W_r      = (const float*)d_in[1];
    const float* mu_r     = (const float*)d_in[2];
    const float* W_k      = (const float*)d_in[3];
    const float* mu_k     = (const float*)d_in[4];
    const float* W_v      = (const float*)d_in[5];
    const float* mu_v     = (const float*)d_in[6];
    const float* W_g      = (const float*)d_in[7];
    const float* mu_g     = (const float*)d_in[8];
    const float* dd_mu    = (const float*)d_in[9];
    const float* dd_W1    = (const float*)d_in[10];
    const float* dd_W2    = (const float*)d_in[11];
    const float* dd_lamda = (const float*)d_in[12];
    const float* w_W1     = (const float*)d_in[13];
    const float* w_W2     = (const float*)d_in[14];
    const float* w_lamda  = (const float*)d_in[15];
    const float* bonus    = (const float*)d_in[16];
    const float* W_o      = (const float*)d_in[17];
    const float* g_norm_w = (const float*)d_in[18];
    float* out = (float*)d_out;

    float *rP,*kP,*vP,*gP,*wP,*xwP,*h1P,*h2P,*oP;
    cudaGetSymbolAddress((void**)&rP,  g_r);
    cudaGetSymbolAddress((void**)&kP,  g_k);
    cudaGetSymbolAddress((void**)&vP,  g_v);
    cudaGetSymbolAddress((void**)&gP,  g_g);
    cudaGetSymbolAddress((void**)&wP,  g_w);
    cudaGetSymbolAddress((void**)&xwP, g_xw);
    cudaGetSymbolAddress((void**)&h1P, g_h1);
    cudaGetSymbolAddress((void**)&h2P, g_h2);
    cudaGetSymbolAddress((void**)&oP,  g_o);

    bf16 *xhP,*xlP,*ohP,*olP;
    bf16 *wrh,*wrl,*wkh,*wkl,*wvh,*wvl,*wgh,*wgl,*woh,*wol;
    cudaGetSymbolAddress((void**)&xhP, g_xh);
    cudaGetSymbolAddress((void**)&xlP, g_xl);
    cudaGetSymbolAddress((void**)&ohP, g_oh);
    cudaGetSymbolAddress((void**)&olP, g_ol);
    cudaGetSymbolAddress((void**)&wrh, g_wrh); cudaGetSymbolAddress((void**)&wrl, g_wrl);
    cudaGetSymbolAddress((void**)&wkh, g_wkh); cudaGetSymbolAddress((void**)&wkl, g_wkl);
    cudaGetSymbolAddress((void**)&wvh, g_wvh); cudaGetSymbolAddress((void**)&wvl, g_wvl);
    cudaGetSymbolAddress((void**)&wgh, g_wgh); cudaGetSymbolAddress((void**)&wgl, g_wgl);
    cudaGetSymbolAddress((void**)&woh, g_woh); cudaGetSymbolAddress((void**)&wol, g_wol);
    const size_t PL = (size_t)MM * DD;

    cudaFuncSetAttribute(gemm_mma, cudaFuncAttributeMaxDynamicSharedMemorySize, MMA_SMEM);

    const dim3 blk(256);
    // launches ordered so ncu (-s 5 -c 1) captures launch #6 = gemm_mma (V proj)
    prep_x<<<(MM*DD/4)/256, 256>>>(x, mu_r, mu_k, mu_v, mu_g);                      // 1
    prep_wT<<<dim3(KK/32, DD/32), dim3(32,8)>>>(W_r, wrh, wrl, DD, KK);             // 2
    prep_wT<<<dim3(VV/32, DD/32), dim3(32,8)>>>(W_v, wvh, wvl, DD, VV);             // 3
    gemm_mma<<<dim3(KK/128, MM/128), blk, MMA_SMEM>>>(xhP+0*PL, xlP+0*PL, wrh, wrl, rP, KK, DD); // 4
    prep_wT<<<dim3(KK/32, DD/32), dim3(32,8)>>>(W_k, wkh, wkl, DD, KK);             // 5
    gemm_mma<<<dim3(VV/128, MM/128), blk, MMA_SMEM>>>(xhP+2*PL, xlP+2*PL, wvh, wvl, vP, VV, DD); // 6 (profiled)
    gemm_mma<<<dim3(KK/128, MM/128), blk, MMA_SMEM>>>(xhP+1*PL, xlP+1*PL, wkh, wkl, kP, KK, DD); // 7
    prep_wT<<<dim3(VV/32, DD/32), dim3(32,8)>>>(W_g, wgh, wgl, DD, VV);             // 8
    gemm_mma<<<dim3(VV/128, MM/128), blk, MMA_SMEM>>>(xhP+3*PL, xlP+3*PL, wgh, wgl, gP, VV, DD); // 9
    prep_wT<<<dim3(DD/32, VV/32), dim3(32,8)>>>(W_o, woh, wol, VV, DD);             // 10

    // LoRA chains
    gemm_skinny<<<MM/128, blk>>>(x,   dd_W1, h1P, DD, dd_mu, 1);                    // 11
    gemm_wide<2><<<dim3(DD/GBN, MM/GBM), blk>>>(h1P, dd_W2, xwP, DD, 32, dd_lamda, x); // 12
    gemm_skinny<<<MM/128, blk>>>(xwP, w_W1,  h2P, DD, nullptr, 0);                  // 13
    gemm_wide<3><<<dim3(KK/GBN, MM/GBM), blk>>>(h2P, w_W2,  wP,  KK, 32, w_lamda, nullptr); // 14

    // recurrence
    scan_kernel<<<BB*HH*2, 256>>>(rP, kP, vP, wP, bonus, oP);                       // 15

    // groupnorm + silu gate -> o planes
    post_kernel<<<MM*HH, 128>>>(oP, gP, g_norm_w);                                  // 16

    // output projection
    gemm_mma<<<dim3(DD/128, MM/128), blk, MMA_SMEM>>>(ohP, olP, woh, wol, out, DD, VV); // 17
}